// round 1
// baseline (speedup 1.0000x reference)
#include <cuda_runtime.h>
#include <cstdint>

#define NPTS 131072
#define BSEG 32
#define SEGSZ (NPTS/BSEG)   // 4096
#define EPSV 1e-7f

typedef unsigned long long ull;

// ---------------- device scratch (no allocations allowed) ----------------
__device__ float g_bufA[NPTS*128*3];
__device__ float g_bufB[NPTS*128*3];
__device__ float g_buf4[(size_t)NPTS*256*3];
__device__ float g_buf5[(size_t)NPTS*256*3];
__device__ float g_dot[(size_t)NPTS*256];
__device__ float g_pool_raw[BSEG*256*3];
__device__ float g_pool_act[BSEG*256*3];
__device__ float g_W1fT[128*128];
__device__ float g_W1dT[128*128];
__device__ float g_W2fT[128*128];
__device__ float g_W2dT[128*128];
__device__ float g_W3T [128*128];
__device__ float g_Wc1T[128*128];
__device__ float g_W4fT[256*256];
__device__ float g_W4dT[256*256];
__device__ float g_W5T [256*256];
__device__ float g_Wc2T[256*256];

// ---------------- packed f32x2 helpers (Blackwell sm_100+) ----------------
__device__ __forceinline__ ull pack2(float v) {
    ull r; asm("mov.b64 %0, {%1, %1};" : "=l"(r) : "f"(v)); return r;
}
__device__ __forceinline__ void ffma2(ull &c, ull a, ull b) {
    asm("fma.rn.f32x2 %0, %1, %2, %0;" : "+l"(c) : "l"(a), "l"(b));
}
__device__ __forceinline__ float2 unpack2(ull v) {
    float2 r; asm("mov.b64 {%0, %1}, %2;" : "=f"(r.x), "=f"(r.y) : "l"(v)); return r;
}

// ---------------- tiny prep kernels ----------------
__global__ void transposeW(const float* __restrict__ src, float* __restrict__ dst,
                           int O, int K) {
    int idx = blockIdx.x * 256 + threadIdx.x;
    if (idx < O * K) {
        int o = idx / K, k = idx - o * K;
        dst[k * O + o] = src[idx];
    }
}

// dstT[k*n + o] = sum_m A[o*n+m] * Bm[m*n+k]   (square n, n = 128 or 256)
__global__ void composeT(const float* __restrict__ A, const float* __restrict__ Bm,
                         float* __restrict__ dstT, int n) {
    int idx = blockIdx.x * 256 + threadIdx.x;
    if (idx >= n * n) return;
    int o = idx % n;
    int k = idx / n;
    float s = 0.f;
    for (int m = 0; m < n; ++m)
        s += A[o * n + m] * Bm[m * n + k];
    dstT[idx] = s;   // idx = k*n + o : coalesced
}

// ---------------- fused VN layer kernel ----------------
// Computes p = Wf @ x, d = Wd @ x over a tile of 32 points (96 gemm columns)
// for 128 output channels (blockIdx.y selects the 128-row block when OFULL=256).
// DOT=false: writes lrelu(p,d) to out.   DOT=true: writes p to out and rowdot(p,d) to dotout.
// CONCAT=true: x rows [0,128) come from xA (pos_emd), rows [128,256) broadcast from xB[seg].
template<int K, int OFULL, bool CONCAT, bool DOT>
__global__ __launch_bounds__(256, 1)
void vn_layer(const float* __restrict__ xA, const float* __restrict__ xB,
              const int* __restrict__ segids,
              const float* __restrict__ WfT, const float* __restrict__ WdT,
              float* __restrict__ out, float* __restrict__ dotout)
{
    extern __shared__ float smem[];
    float* sWf = smem;                      // [128][128]  k-major chunk of WfT
    float* sWd = smem + 128*128;            // [128][128]
    float* sX  = smem + 2*128*128;          // [32][385]   per-point rows (384 used, +1 pad)
    float* sOut = smem;                     // epilogue alias: [128][99]
    float* sDot = smem + 128*99;            // epilogue alias: [32][129]

    const int tid = threadIdx.x;
    const int rg = tid >> 4;                // 0..15  -> rows 8*rg .. 8*rg+7
    const int cg = tid & 15;                // 0..15  -> points 2*cg, 2*cg+1
    const int ptBase = blockIdx.x * 32;
    const int obase  = blockIdx.y * 128;

    int seg = 0;
    if (CONCAT) seg = segids[ptBase];

    ull accF[4][6], accD[4][6];
    #pragma unroll
    for (int p = 0; p < 4; ++p)
        #pragma unroll
        for (int j = 0; j < 6; ++j) { accF[p][j] = 0ull; accD[p][j] = 0ull; }

    for (int kb = 0; kb < K; kb += 128) {
        __syncthreads();
        // ---- load weight chunks (k-major, conflict-free linear copy) ----
        #pragma unroll
        for (int t = tid * 4; t < 128*128; t += 1024) {
            int k = t >> 7, o = t & 127;
            *(float4*)(sWf + t) = *(const float4*)(WfT + (size_t)(kb + k) * OFULL + obase + o);
            *(float4*)(sWd + t) = *(const float4*)(WdT + (size_t)(kb + k) * OFULL + obase + o);
        }
        // ---- load x tile ----
        if (!CONCAT || kb < 128) {
            const int rs = CONCAT ? 384 : K * 3;
            const float* xs0 = xA + (size_t)ptBase * rs + kb * 3;
            #pragma unroll
            for (int t = tid * 4; t < 32*384; t += 1024) {
                int pt = t / 384, l = t - pt * 384;
                float4 v = *(const float4*)(xs0 + (size_t)pt * rs + l);
                float* dst = sX + pt * 385 + l;
                dst[0] = v.x; dst[1] = v.y; dst[2] = v.z; dst[3] = v.w;
            }
        } else {
            // broadcast pooled features (same 384 floats for every point in the tile)
            const float* xs0 = xB + (size_t)seg * 384;
            for (int t = tid; t < 32*384; t += 256) {
                int pt = t / 384, l = t - pt * 384;
                sX[pt * 385 + l] = xs0[l];
            }
        }
        __syncthreads();

        const float* bp0 = sX + (2 * cg) * 385;
        #pragma unroll 4
        for (int k = 0; k < 128; ++k) {
            const float* wf = sWf + (k << 7) + 8 * rg;
            const float* wd = sWd + (k << 7) + 8 * rg;
            ulonglong2 af01 = *(const ulonglong2*)(wf);
            ulonglong2 af23 = *(const ulonglong2*)(wf + 4);
            ulonglong2 ad01 = *(const ulonglong2*)(wd);
            ulonglong2 ad23 = *(const ulonglong2*)(wd + 4);
            ull af[4] = { af01.x, af01.y, af23.x, af23.y };
            ull ad[4] = { ad01.x, ad01.y, ad23.x, ad23.y };
            const float* b0 = bp0 + 3 * k;
            ull bd[6];
            bd[0] = pack2(b0[0]);   bd[1] = pack2(b0[1]);   bd[2] = pack2(b0[2]);
            bd[3] = pack2(b0[385]); bd[4] = pack2(b0[386]); bd[5] = pack2(b0[387]);
            #pragma unroll
            for (int p = 0; p < 4; ++p)
                #pragma unroll
                for (int j = 0; j < 6; ++j) {
                    ffma2(accF[p][j], af[p], bd[j]);
                    ffma2(accD[p][j], ad[p], bd[j]);
                }
        }
    }

    __syncthreads();   // smem about to be reused for epilogue staging

    // ---- epilogue: lrelu or (p, rowdot) ----
    #pragma unroll
    for (int pr = 0; pr < 4; ++pr) {
        float2 fv[6], dv[6];
        #pragma unroll
        for (int j = 0; j < 6; ++j) { fv[j] = unpack2(accF[pr][j]); dv[j] = unpack2(accD[pr][j]); }
        int r0 = 8 * rg + 2 * pr;
        #pragma unroll
        for (int h = 0; h < 2; ++h) {
            int r = r0 + h;
            #pragma unroll
            for (int q = 0; q < 2; ++q) {
                float p0 = h ? fv[3*q+0].y : fv[3*q+0].x;
                float p1 = h ? fv[3*q+1].y : fv[3*q+1].x;
                float p2 = h ? fv[3*q+2].y : fv[3*q+2].x;
                float e0 = h ? dv[3*q+0].y : dv[3*q+0].x;
                float e1 = h ? dv[3*q+1].y : dv[3*q+1].x;
                float e2 = h ? dv[3*q+2].y : dv[3*q+2].x;
                float dt = p0*e0 + p1*e1 + p2*e2;
                int pt = 2 * cg + q;
                float* so = sOut + r * 99 + pt * 3;
                if (DOT) {
                    sDot[pt * 129 + r] = dt;
                    so[0] = p0; so[1] = p1; so[2] = p2;
                } else {
                    float dn = e0*e0 + e1*e1 + e2*e2;
                    float s = dt / (dn + EPSV);
                    if (dt >= 0.f) { so[0] = p0;         so[1] = p1;         so[2] = p2; }
                    else           { so[0] = p0 - s*e0;  so[1] = p1 - s*e1;  so[2] = p2 - s*e2; }
                }
            }
        }
    }
    __syncthreads();

    // ---- coalesced writeback ----
    {
        const size_t orow = (size_t)OFULL * 3;
        for (int t = tid; t < 128 * 96; t += 256) {
            int pt = t / 384, m = t - pt * 384;
            int c = m / 3, i = m - c * 3;
            out[(size_t)(ptBase + pt) * orow + (size_t)obase * 3 + m] = sOut[c * 99 + pt * 3 + i];
        }
        if (DOT) {
            for (int t = tid; t < 32 * 128; t += 256) {
                int pt = t >> 7, c = t & 127;
                dotout[(size_t)(ptBase + pt) * OFULL + obase + c] = sDot[pt * 129 + c];
            }
        }
    }
}

// ---------------- segment argmax pool + gather ----------------
// grid: (BSEG, C/32); block 256 = 8 strided groups x 32 channels
__global__ void pool_kernel(const float* __restrict__ dotv, const float* __restrict__ g,
                            float* __restrict__ pooled, int C)
{
    int seg = blockIdx.x;
    int cbase = blockIdx.y * 32;
    int tid = threadIdx.x;
    int c = tid & 31, tg = tid >> 5;

    float best = -__int_as_float(0x7f800000);  // -inf
    int bidx = 0x7fffffff;
    int base = seg * SEGSZ;
    for (int t = tg; t < SEGSZ; t += 8) {
        float v = dotv[(size_t)(base + t) * C + cbase + c];
        if (v > best) { best = v; bidx = base + t; }   // strict > keeps smallest idx in-thread
    }
    __shared__ float sv[256];
    __shared__ int   si[256];
    sv[tid] = best; si[tid] = bidx;
    __syncthreads();
    if (tg == 0) {
        for (int q = 1; q < 8; ++q) {
            float v = sv[q * 32 + c]; int ix = si[q * 32 + c];
            if (v > best || (v == best && ix < bidx)) { best = v; bidx = ix; }
        }
        int cc = cbase + c;
        const float* gs = g + ((size_t)bidx * C + cc) * 3;
        float* pd = pooled + ((size_t)seg * C + cc) * 3;
        pd[0] = gs[0]; pd[1] = gs[1]; pd[2] = gs[2];
    }
}

// ---------------- small VNLeakyReLU on pooled [B, C, 3] ----------------
__global__ void relu_small(const float* __restrict__ pooled, const float* __restrict__ Wr,
                           float* __restrict__ out, int C)
{
    __shared__ float sx[256 * 3];
    int seg = blockIdx.x, c = threadIdx.x;
    for (int t = c; t < C * 3; t += blockDim.x) sx[t] = pooled[(size_t)seg * C * 3 + t];
    __syncthreads();
    float d0 = 0.f, d1 = 0.f, d2 = 0.f;
    const float* w = Wr + (size_t)c * C;
    for (int k = 0; k < C; ++k) {
        float wv = w[k];
        d0 += wv * sx[3*k]; d1 += wv * sx[3*k+1]; d2 += wv * sx[3*k+2];
    }
    float x0 = sx[3*c], x1 = sx[3*c+1], x2 = sx[3*c+2];
    float dt = x0*d0 + x1*d1 + x2*d2;
    float dn = d0*d0 + d1*d1 + d2*d2;
    float s = dt / (dn + EPSV);
    float* o = out + (size_t)seg * C * 3 + 3 * c;
    if (dt >= 0.f) { o[0] = x0;        o[1] = x1;        o[2] = x2; }
    else           { o[0] = x0 - s*d0; o[1] = x1 - s*d1; o[2] = x2 - s*d2; }
}

// ---------------- host launcher ----------------
extern "C" void kernel_launch(void* const* d_in, const int* in_sizes, int n_in,
                              void* d_out, int out_size)
{
    const float* pos    = (const float*)d_in[0];
    const int*   segids = (const int*)  d_in[1];
    const float* W1f = (const float*)d_in[2];
    const float* W1d = (const float*)d_in[3];
    const float* W2f = (const float*)d_in[4];
    const float* W2d = (const float*)d_in[5];
    const float* W3  = (const float*)d_in[6];
    const float* Wd1 = (const float*)d_in[7];
    const float* Wr3 = (const float*)d_in[8];
    const float* W4f = (const float*)d_in[9];
    const float* W4d = (const float*)d_in[10];
    const float* W5  = (const float*)d_in[11];
    const float* Wd2 = (const float*)d_in[12];
    const float* Wr5 = (const float*)d_in[13];
    float* outp = (float*)d_out;

    float *bufA, *bufB, *buf4, *buf5, *dotb, *praw, *pact;
    float *W1fT, *W1dT, *W2fT, *W2dT, *W3T, *Wc1T, *W4fT, *W4dT, *W5T, *Wc2T;
    cudaGetSymbolAddress((void**)&bufA, g_bufA);
    cudaGetSymbolAddress((void**)&bufB, g_bufB);
    cudaGetSymbolAddress((void**)&buf4, g_buf4);
    cudaGetSymbolAddress((void**)&buf5, g_buf5);
    cudaGetSymbolAddress((void**)&dotb, g_dot);
    cudaGetSymbolAddress((void**)&praw, g_pool_raw);
    cudaGetSymbolAddress((void**)&pact, g_pool_act);
    cudaGetSymbolAddress((void**)&W1fT, g_W1fT);
    cudaGetSymbolAddress((void**)&W1dT, g_W1dT);
    cudaGetSymbolAddress((void**)&W2fT, g_W2fT);
    cudaGetSymbolAddress((void**)&W2dT, g_W2dT);
    cudaGetSymbolAddress((void**)&W3T,  g_W3T);
    cudaGetSymbolAddress((void**)&Wc1T, g_Wc1T);
    cudaGetSymbolAddress((void**)&W4fT, g_W4fT);
    cudaGetSymbolAddress((void**)&W4dT, g_W4dT);
    cudaGetSymbolAddress((void**)&W5T,  g_W5T);
    cudaGetSymbolAddress((void**)&Wc2T, g_Wc2T);

    // ---- prep: transposed weights + composed direction weights ----
    transposeW<<<(128*128 + 255)/256, 256>>>(W1f, W1fT, 128, 128);
    transposeW<<<(128*128 + 255)/256, 256>>>(W1d, W1dT, 128, 128);
    transposeW<<<(128*128 + 255)/256, 256>>>(W2f, W2fT, 128, 128);
    transposeW<<<(128*128 + 255)/256, 256>>>(W2d, W2dT, 128, 128);
    transposeW<<<(128*128 + 255)/256, 256>>>(W3,  W3T,  128, 128);
    transposeW<<<(256*256 + 255)/256, 256>>>(W4f, W4fT, 256, 256);
    transposeW<<<(256*256 + 255)/256, 256>>>(W4d, W4dT, 256, 256);
    transposeW<<<(256*256 + 255)/256, 256>>>(W5,  W5T,  256, 256);
    composeT<<<(128*128)/256, 256>>>(Wd1, W3, Wc1T, 128);   // Wc1 = Wd1 @ W3 (stored k-major)
    composeT<<<(256*256)/256, 256>>>(Wd2, W5, Wc2T, 256);   // Wc2 = Wd2 @ W5

    const size_t smem = (size_t)(2*128*128 + 32*385) * sizeof(float);  // 180,352 B
    cudaFuncSetAttribute(vn_layer<128,128,false,false>, cudaFuncAttributeMaxDynamicSharedMemorySize, (int)smem);
    cudaFuncSetAttribute(vn_layer<128,128,false,true >, cudaFuncAttributeMaxDynamicSharedMemorySize, (int)smem);
    cudaFuncSetAttribute(vn_layer<256,256,true ,false>, cudaFuncAttributeMaxDynamicSharedMemorySize, (int)smem);
    cudaFuncSetAttribute(vn_layer<256,256,false,true >, cudaFuncAttributeMaxDynamicSharedMemorySize, (int)smem);

    dim3 gA(NPTS/32, 1), gB(NPTS/32, 2);
    // vn1, vn2 (lrelu layers, C=128)
    vn_layer<128,128,false,false><<<gA, 256, smem>>>(pos,  nullptr, segids, W1fT, W1dT, bufA, nullptr);
    vn_layer<128,128,false,false><<<gA, 256, smem>>>(bufA, nullptr, segids, W2fT, W2dT, bufB, nullptr);
    // vn3 + pool1 direction dots (g3 = W3@g2, dot via Wc1 = Wd1@W3)
    vn_layer<128,128,false,true ><<<gA, 256, smem>>>(bufB, nullptr, segids, W3T, Wc1T, bufA, dotb);
    pool_kernel<<<dim3(BSEG, 4), 256>>>(dotb, bufA, praw, 128);
    relu_small<<<BSEG, 128>>>(praw, Wr3, pact, 128);
    // vn4 on concat(pos, broadcast pooled)
    vn_layer<256,256,true ,false><<<gB, 256, smem>>>(pos, pact, segids, W4fT, W4dT, buf4, nullptr);
    // vn5 + pool2 direction dots
    vn_layer<256,256,false,true ><<<gB, 256, smem>>>(buf4, nullptr, segids, W5T, Wc2T, buf5, dotb);
    pool_kernel<<<dim3(BSEG, 8), 256>>>(dotb, buf5, praw, 256);
    relu_small<<<BSEG, 256>>>(praw, Wr5, outp, 256);
    (void)in_sizes; (void)n_in; (void)out_size;
}

// round 2
// speedup vs baseline: 1.1566x; 1.1566x over previous
#include <cuda_runtime.h>
#include <cstdint>

#define NPTS 131072
#define BSEG 32
#define NTILES 4096          // NPTS/32 ; 128 tiles per segment, tiles never straddle segments
#define EPSV 1e-7f

typedef unsigned long long ull;
typedef unsigned int uint;

// ---------------- device scratch (no allocations allowed) ----------------
__device__ float g_bufA[(size_t)NPTS*128*3];
__device__ float g_bufB[(size_t)NPTS*128*3];
__device__ float g_buf4[(size_t)NPTS*256*3];
__device__ float g_praw[BSEG*256*3];
__device__ float g_pact[BSEG*256*3];
__device__ float g_biasF[BSEG*256*3];
__device__ float g_biasD[BSEG*256*3];
__device__ ull   g_cand[BSEG*256];
__device__ float g_W1fT[128*128];
__device__ float g_W1dT[128*128];
__device__ float g_W2fT[128*128];
__device__ float g_W2dT[128*128];
__device__ float g_W3T [128*128];
__device__ float g_Wc1T[128*128];
__device__ float g_W4fT[256*256];
__device__ float g_W4dT[256*256];
__device__ float g_W5T [256*256];
__device__ float g_Wc2T[256*256];

// ---------------- packed f32x2 helpers (Blackwell sm_100+) ----------------
__device__ __forceinline__ ull pack2(float v) {
    ull r; asm("mov.b64 %0, {%1, %1};" : "=l"(r) : "f"(v)); return r;
}
__device__ __forceinline__ void ffma2(ull &c, ull a, ull b) {
    asm("fma.rn.f32x2 %0, %1, %2, %0;" : "+l"(c) : "l"(a), "l"(b));
}
__device__ __forceinline__ float2 unpack2(ull v) {
    float2 r; asm("mov.b64 {%0, %1}, %2;" : "=f"(r.x), "=f"(r.y) : "l"(v)); return r;
}

// ---------------- cp.async helpers ----------------
__device__ __forceinline__ uint s2u(const void* p) {
    return (uint)__cvta_generic_to_shared(p);
}
__device__ __forceinline__ void cpa4(uint dst, const float* src) {
    asm volatile("cp.async.ca.shared.global [%0], [%1], 4;" :: "r"(dst), "l"(src));
}
#define CP_COMMIT() asm volatile("cp.async.commit_group;")
#define CP_WAIT1()  asm volatile("cp.async.wait_group 1;")

// monotonic float->uint key (order-preserving for all finite floats)
__device__ __forceinline__ uint fkey(float v) {
    uint u = __float_as_uint(v);
    return (u & 0x80000000u) ? ~u : (u | 0x80000000u);
}

// ---------------- tiny prep kernels ----------------
__global__ void transposeW(const float* __restrict__ src, float* __restrict__ dst,
                           int O, int K) {
    int idx = blockIdx.x * 256 + threadIdx.x;
    if (idx < O * K) {
        int o = idx / K, k = idx - o * K;
        dst[k * O + o] = src[idx];
    }
}

// dstT[k*n + o] = sum_m A[o*n+m] * Bm[m*n+k]
__global__ void composeT(const float* __restrict__ A, const float* __restrict__ Bm,
                         float* __restrict__ dstT, int n) {
    int idx = blockIdx.x * 256 + threadIdx.x;
    if (idx >= n * n) return;
    int o = idx % n;
    int k = idx / n;
    float s = 0.f;
    for (int m = 0; m < n; ++m)
        s += A[o * n + m] * Bm[m * n + k];
    dstT[idx] = s;
}

// biasF/biasD[seg][o][i] = sum_{c<128} W4{f,d}[o][128+c] * pact[seg][c][i]
__global__ void bias4_kernel(const float* __restrict__ W4f, const float* __restrict__ W4d,
                             const float* __restrict__ pact,
                             float* __restrict__ bF, float* __restrict__ bD)
{
    __shared__ float sp[128*3];
    int seg = blockIdx.x, o = threadIdx.x;   // 256 threads
    for (int t = o; t < 128*3; t += 256) sp[t] = pact[(size_t)seg*128*3 + t];
    __syncthreads();
    float f0=0,f1=0,f2=0,d0=0,d1=0,d2=0;
    const float* wf = W4f + (size_t)o*256 + 128;
    const float* wd = W4d + (size_t)o*256 + 128;
    #pragma unroll 4
    for (int c = 0; c < 128; ++c) {
        float a = wf[c], b = wd[c];
        float x0 = sp[3*c], x1 = sp[3*c+1], x2 = sp[3*c+2];
        f0 += a*x0; f1 += a*x1; f2 += a*x2;
        d0 += b*x0; d1 += b*x1; d2 += b*x2;
    }
    float* pf = bF + ((size_t)seg*256 + o)*3;
    float* pd = bD + ((size_t)seg*256 + o)*3;
    pf[0]=f0; pf[1]=f1; pf[2]=f2;
    pd[0]=d0; pd[1]=d1; pd[2]=d2;
}

// ---------------- persistent fused VN layer ----------------
// o-block = 64 channels (blockIdx.x), 32-point tiles strided by gridDim.y walkers.
// Weights resident in smem for the whole layer; x-tiles double-buffered via cp.async.
// DOT=true: computes dot(p, d) per (point, channel) and folds the segment-argmax
//           into packed-u64 atomicMax (no per-point outputs written).
// BIAS=true: adds per-(segment, channel) bias (vn4 concat trick) before lrelu.
template<int KCH, int NOtot, bool BIAS, bool DOT>
__global__ void __launch_bounds__(256, 1)
vn_persist(const float* __restrict__ x, const int* __restrict__ segids,
           const float* __restrict__ WfT, const float* __restrict__ WdT,
           const float* __restrict__ bF, const float* __restrict__ bD,
           float* __restrict__ out, ull* __restrict__ cand)
{
    constexpr int K  = KCH * 128;
    constexpr int RS = K * 3;        // x row stride (floats)
    constexpr int XB = 32 * 385;     // per-stage x buffer (floats), pad 385 keeps banks clean

    extern __shared__ float smem[];
    float* sWf = smem;                       // [K][64]
    float* sWd = smem + K*64;                // [K][64]
    float* sX  = smem + 2*K*64;              // 2 x [32][385]
    float* sStage = sX + 2*XB;               // [64][97] (only !DOT)

    const int tid = threadIdx.x;
    const int rg = tid >> 4;                 // 0..15 -> rows 4*rg..4*rg+3
    const int cg = tid & 15;                 // 0..15 -> pts 2*cg, 2*cg+1
    const int obase = blockIdx.x * 64;
    const int nwalk = gridDim.y;

    // ---- resident weight load (once per block) ----
    for (int t = tid; t < K*16; t += 256) {
        int k = t >> 4, c4 = t & 15;
        ((float4*)sWf)[t] = *(const float4*)(WfT + (size_t)k*NOtot + obase + 4*c4);
        ((float4*)sWd)[t] = *(const float4*)(WdT + (size_t)k*NOtot + obase + 4*c4);
    }

    // ---- pipeline bootstrap: prefetch chunk 0 and 1 ----
    int tp = blockIdx.y, khp = 0;
    auto prefetch = [&](int tile, int kh, int buf) {
        const float* s0 = x + (size_t)tile*32*RS + kh*384;
        float* d0 = sX + buf*XB;
        #pragma unroll 4
        for (int it = 0; it < 48; ++it) {
            int t = tid + it*256;
            int pt = t / 384, l = t - pt*384;
            cpa4(s2u(d0 + pt*385 + l), s0 + (size_t)pt*RS + l);
        }
    };
    auto adv = [&]() { if (++khp == KCH) { khp = 0; tp += nwalk; } };

    prefetch(tp, khp, 0); CP_COMMIT(); adv();
    if (tp < NTILES) prefetch(tp, khp, 1);
    CP_COMMIT(); adv();

    int cur = 0;
    ull accF[2][6], accD[2][6];

    for (int t = blockIdx.y; t < NTILES; t += nwalk) {
        #pragma unroll
        for (int pr = 0; pr < 2; ++pr)
            #pragma unroll
            for (int j = 0; j < 6; ++j) { accF[pr][j] = 0ull; accD[pr][j] = 0ull; }

        #pragma unroll
        for (int kh = 0; kh < KCH; ++kh) {
            CP_WAIT1();
            __syncthreads();    // chunk (t, kh) ready in sX[cur]

            const float* bp0 = sX + cur*XB + (2*cg)*385;
            const float* wfp = sWf + kh*128*64 + 4*rg;
            const float* wdp = sWd + kh*128*64 + 4*rg;
            #pragma unroll 4
            for (int k = 0; k < 128; ++k) {
                ulonglong2 af = *(const ulonglong2*)(wfp + k*64);  // rows (4rg,4rg+1),(4rg+2,4rg+3)
                ulonglong2 ad = *(const ulonglong2*)(wdp + k*64);
                const float* b0 = bp0 + 3*k;
                ull bd[6];
                bd[0] = pack2(b0[0]);   bd[1] = pack2(b0[1]);   bd[2] = pack2(b0[2]);
                bd[3] = pack2(b0[385]); bd[4] = pack2(b0[386]); bd[5] = pack2(b0[387]);
                #pragma unroll
                for (int j = 0; j < 6; ++j) {
                    ffma2(accF[0][j], af.x, bd[j]);
                    ffma2(accF[1][j], af.y, bd[j]);
                    ffma2(accD[0][j], ad.x, bd[j]);
                    ffma2(accD[1][j], ad.y, bd[j]);
                }
            }
            __syncthreads();    // everyone done reading sX[cur]
            if (tp < NTILES) prefetch(tp, khp, cur);
            CP_COMMIT();
            adv();
            cur ^= 1;
        }

        const int seg = segids[t * 32];

        if (DOT) {
            // ---- fused segment argmax on dot(p, d) ----
            const int pt0 = t*32 + 2*cg;
            #pragma unroll
            for (int pr = 0; pr < 2; ++pr) {
                float2 f[6], e[6];
                #pragma unroll
                for (int j = 0; j < 6; ++j) { f[j] = unpack2(accF[pr][j]); e[j] = unpack2(accD[pr][j]); }
                #pragma unroll
                for (int h = 0; h < 2; ++h) {
                    float dt0, dt1;
                    if (h == 0) {
                        dt0 = f[0].x*e[0].x + f[1].x*e[1].x + f[2].x*e[2].x;
                        dt1 = f[3].x*e[3].x + f[4].x*e[4].x + f[5].x*e[5].x;
                    } else {
                        dt0 = f[0].y*e[0].y + f[1].y*e[1].y + f[2].y*e[2].y;
                        dt1 = f[3].y*e[3].y + f[4].y*e[4].y + f[5].y*e[5].y;
                    }
                    float v; int idx;
                    if (dt1 > dt0) { v = dt1; idx = pt0 + 1; } else { v = dt0; idx = pt0; }
                    #pragma unroll
                    for (int m = 1; m <= 8; m <<= 1) {
                        float ov = __shfl_xor_sync(0xffffffffu, v, m);
                        int   oi = __shfl_xor_sync(0xffffffffu, idx, m);
                        if (ov > v || (ov == v && oi < idx)) { v = ov; idx = oi; }
                    }
                    if (cg == 0) {
                        ull key = ((ull)fkey(v) << 32) | (uint)(~(uint)idx);
                        atomicMax(&cand[seg*NOtot + obase + 4*rg + 2*pr + h], key);
                    }
                }
            }
        } else {
            // ---- lrelu (+bias) epilogue, staged for coalesced writeback ----
            #pragma unroll
            for (int pr = 0; pr < 2; ++pr) {
                float2 f[6], e[6];
                #pragma unroll
                for (int j = 0; j < 6; ++j) { f[j] = unpack2(accF[pr][j]); e[j] = unpack2(accD[pr][j]); }
                #pragma unroll
                for (int h = 0; h < 2; ++h) {
                    int r = 4*rg + 2*pr + h;
                    float bf0=0.f, bf1=0.f, bf2=0.f, bd0=0.f, bd1=0.f, bd2=0.f;
                    if (BIAS) {
                        const float* pf = bF + ((size_t)seg*NOtot + obase + r)*3;
                        const float* pd = bD + ((size_t)seg*NOtot + obase + r)*3;
                        bf0 = pf[0]; bf1 = pf[1]; bf2 = pf[2];
                        bd0 = pd[0]; bd1 = pd[1]; bd2 = pd[2];
                    }
                    #pragma unroll
                    for (int q = 0; q < 2; ++q) {
                        float p0 = (h ? f[3*q+0].y : f[3*q+0].x) + bf0;
                        float p1 = (h ? f[3*q+1].y : f[3*q+1].x) + bf1;
                        float p2 = (h ? f[3*q+2].y : f[3*q+2].x) + bf2;
                        float e0 = (h ? e[3*q+0].y : e[3*q+0].x) + bd0;
                        float e1 = (h ? e[3*q+1].y : e[3*q+1].x) + bd1;
                        float e2 = (h ? e[3*q+2].y : e[3*q+2].x) + bd2;
                        float dt = p0*e0 + p1*e1 + p2*e2;
                        float dn = e0*e0 + e1*e1 + e2*e2;
                        float s = dt / (dn + EPSV);
                        float* so = sStage + r*97 + (2*cg + q)*3;
                        if (dt >= 0.f) { so[0] = p0;        so[1] = p1;        so[2] = p2; }
                        else           { so[0] = p0 - s*e0; so[1] = p1 - s*e1; so[2] = p2 - s*e2; }
                    }
                }
            }
            __syncthreads();
            const size_t orow = (size_t)NOtot * 3;
            for (int tt = tid; tt < 32*192; tt += 256) {
                int pt = tt / 192, m = tt - pt*192;
                out[(size_t)(t*32 + pt)*orow + obase*3 + m] = sStage[(m/3)*97 + pt*3 + (m%3)];
            }
            // next-iteration's post-wait __syncthreads fences sStage reuse
        }
    }
}

// ---------------- winner recompute + gather ----------------
// pooled[seg][ch][:] = W @ src[winner_idx] for the argmax winner of (seg, ch)
template<int KSRC, int NOtot>
__global__ void winner_gather(const ull* __restrict__ cand, const float* __restrict__ src,
                              const float* __restrict__ WT, float* __restrict__ pooled)
{
    int seg = blockIdx.x, ch = threadIdx.x;          // NOtot threads
    ull cv = cand[seg*NOtot + ch];
    uint idx = ~((uint)(cv & 0xffffffffull));
    const float* row = src + (size_t)idx * (KSRC*3);
    float a0 = 0.f, a1 = 0.f, a2 = 0.f;
    #pragma unroll 4
    for (int c = 0; c < KSRC; ++c) {
        float w = WT[(size_t)c*NOtot + ch];
        a0 += w*row[3*c]; a1 += w*row[3*c+1]; a2 += w*row[3*c+2];
    }
    float* o = pooled + ((size_t)seg*NOtot + ch)*3;
    o[0] = a0; o[1] = a1; o[2] = a2;
}

// ---------------- small VNLeakyReLU on pooled [B, C, 3] ----------------
__global__ void relu_small(const float* __restrict__ pooled, const float* __restrict__ Wr,
                           float* __restrict__ out, int C)
{
    __shared__ float sx[256 * 3];
    int seg = blockIdx.x, c = threadIdx.x;
    for (int t = c; t < C * 3; t += blockDim.x) sx[t] = pooled[(size_t)seg * C * 3 + t];
    __syncthreads();
    float d0 = 0.f, d1 = 0.f, d2 = 0.f;
    const float* w = Wr + (size_t)c * C;
    for (int k = 0; k < C; ++k) {
        float wv = w[k];
        d0 += wv * sx[3*k]; d1 += wv * sx[3*k+1]; d2 += wv * sx[3*k+2];
    }
    float x0 = sx[3*c], x1 = sx[3*c+1], x2 = sx[3*c+2];
    float dt = x0*d0 + x1*d1 + x2*d2;
    float dn = d0*d0 + d1*d1 + d2*d2;
    float s = dt / (dn + EPSV);
    float* o = out + (size_t)seg * C * 3 + 3 * c;
    if (dt >= 0.f) { o[0] = x0;        o[1] = x1;        o[2] = x2; }
    else           { o[0] = x0 - s*d0; o[1] = x1 - s*d1; o[2] = x2 - s*d2; }
}

// ---------------- host launcher ----------------
extern "C" void kernel_launch(void* const* d_in, const int* in_sizes, int n_in,
                              void* d_out, int out_size)
{
    const float* pos    = (const float*)d_in[0];
    const int*   segids = (const int*)  d_in[1];
    const float* W1f = (const float*)d_in[2];
    const float* W1d = (const float*)d_in[3];
    const float* W2f = (const float*)d_in[4];
    const float* W2d = (const float*)d_in[5];
    const float* W3  = (const float*)d_in[6];
    const float* Wd1 = (const float*)d_in[7];
    const float* Wr3 = (const float*)d_in[8];
    const float* W4f = (const float*)d_in[9];
    const float* W4d = (const float*)d_in[10];
    const float* W5  = (const float*)d_in[11];
    const float* Wd2 = (const float*)d_in[12];
    const float* Wr5 = (const float*)d_in[13];
    float* outp = (float*)d_out;

    float *bufA, *bufB, *buf4, *praw, *pact, *bF, *bD;
    ull* cand;
    float *W1fT, *W1dT, *W2fT, *W2dT, *W3T, *Wc1T, *W4fT, *W4dT, *W5T, *Wc2T;
    cudaGetSymbolAddress((void**)&bufA, g_bufA);
    cudaGetSymbolAddress((void**)&bufB, g_bufB);
    cudaGetSymbolAddress((void**)&buf4, g_buf4);
    cudaGetSymbolAddress((void**)&praw, g_praw);
    cudaGetSymbolAddress((void**)&pact, g_pact);
    cudaGetSymbolAddress((void**)&bF,   g_biasF);
    cudaGetSymbolAddress((void**)&bD,   g_biasD);
    cudaGetSymbolAddress((void**)&cand, g_cand);
    cudaGetSymbolAddress((void**)&W1fT, g_W1fT);
    cudaGetSymbolAddress((void**)&W1dT, g_W1dT);
    cudaGetSymbolAddress((void**)&W2fT, g_W2fT);
    cudaGetSymbolAddress((void**)&W2dT, g_W2dT);
    cudaGetSymbolAddress((void**)&W3T,  g_W3T);
    cudaGetSymbolAddress((void**)&Wc1T, g_Wc1T);
    cudaGetSymbolAddress((void**)&W4fT, g_W4fT);
    cudaGetSymbolAddress((void**)&W4dT, g_W4dT);
    cudaGetSymbolAddress((void**)&W5T,  g_W5T);
    cudaGetSymbolAddress((void**)&Wc2T, g_Wc2T);

    // ---- prep ----
    transposeW<<<64, 256>>>(W1f, W1fT, 128, 128);
    transposeW<<<64, 256>>>(W1d, W1dT, 128, 128);
    transposeW<<<64, 256>>>(W2f, W2fT, 128, 128);
    transposeW<<<64, 256>>>(W2d, W2dT, 128, 128);
    transposeW<<<64, 256>>>(W3,  W3T,  128, 128);
    transposeW<<<256, 256>>>(W4f, W4fT, 256, 256);
    transposeW<<<256, 256>>>(W4d, W4dT, 256, 256);
    transposeW<<<256, 256>>>(W5,  W5T,  256, 256);
    composeT<<<64, 256>>>(Wd1, W3, Wc1T, 128);    // Wc1 = Wd1 @ W3 (k-major)
    composeT<<<256, 256>>>(Wd2, W5, Wc2T, 256);   // Wc2 = Wd2 @ W5

    const int smemL  = (2*128*64 + 2*32*385 + 64*97) * 4;   // 188,928 (lrelu layers)
    const int smemD1 = (2*128*64 + 2*32*385) * 4;           // 164,096 (vn3 dot)
    const int smemD2 = (2*256*64 + 2*32*385) * 4;           // 229,632 (vn5 dot)
    cudaFuncSetAttribute(vn_persist<1,128,false,false>, cudaFuncAttributeMaxDynamicSharedMemorySize, smemL);
    cudaFuncSetAttribute(vn_persist<1,128,false,true >, cudaFuncAttributeMaxDynamicSharedMemorySize, smemD1);
    cudaFuncSetAttribute(vn_persist<1,256,true ,false>, cudaFuncAttributeMaxDynamicSharedMemorySize, smemL);
    cudaFuncSetAttribute(vn_persist<2,256,false,true >, cudaFuncAttributeMaxDynamicSharedMemorySize, smemD2);

    // ---- vn1, vn2 ----
    vn_persist<1,128,false,false><<<dim3(2,74), 256, smemL>>>(pos,  segids, W1fT, W1dT, nullptr, nullptr, bufA, nullptr);
    vn_persist<1,128,false,false><<<dim3(2,74), 256, smemL>>>(bufA, segids, W2fT, W2dT, nullptr, nullptr, bufB, nullptr);

    // ---- vn3 + fused pool1 argmax ----
    cudaMemsetAsync(cand, 0, BSEG*256*sizeof(ull));
    vn_persist<1,128,false,true ><<<dim3(2,74), 256, smemD1>>>(bufB, segids, W3T, Wc1T, nullptr, nullptr, nullptr, cand);
    winner_gather<128,128><<<BSEG, 128>>>(cand, bufB, W3T, praw);
    relu_small<<<BSEG, 128>>>(praw, Wr3, pact, 128);

    // ---- vn4 (concat half folded into per-segment bias) ----
    bias4_kernel<<<BSEG, 256>>>(W4f, W4d, pact, bF, bD);
    vn_persist<1,256,true ,false><<<dim3(4,37), 256, smemL>>>(pos, segids, W4fT, W4dT, bF, bD, buf4, nullptr);

    // ---- vn5 + fused pool2 argmax ----
    cudaMemsetAsync(cand, 0, BSEG*256*sizeof(ull));
    vn_persist<2,256,false,true ><<<dim3(4,37), 256, smemD2>>>(buf4, segids, W5T, Wc2T, nullptr, nullptr, nullptr, cand);
    winner_gather<256,256><<<BSEG, 256>>>(cand, buf4, W5T, praw);
    relu_small<<<BSEG, 256>>>(praw, Wr5, outp, 256);

    (void)in_sizes; (void)n_in; (void)out_size;
}

// round 4
// speedup vs baseline: 1.1594x; 1.0025x over previous
#include <cuda_runtime.h>
#include <cstdint>

#define NPTS 131072
#define BSEG 32
#define TPTS 64               // points per tile
#define NTILES (NPTS/TPTS)    // 2048 ; 64 tiles/segment, tiles never straddle segments
#define EPSV 1e-7f

typedef unsigned long long ull;
typedef unsigned int uint;

// ---------------- device scratch ----------------
__device__ float g_posT[(size_t)NPTS*128*3];
__device__ float g_bufA[(size_t)NPTS*128*3];
__device__ float g_bufB[(size_t)NPTS*128*3];
__device__ float g_buf4[(size_t)NPTS*256*3];
__device__ float g_praw[BSEG*256*3];
__device__ float g_pact[BSEG*256*3];
__device__ float g_biasF[BSEG*256*3];
__device__ float g_biasD[BSEG*256*3];
__device__ ull   g_cand[BSEG*256];
// dup'd k-major weights: [k][o] float2 = (w,w)
__device__ float2 g_W1fD[128*128];
__device__ float2 g_W1dD[128*128];
__device__ float2 g_W2fD[128*128];
__device__ float2 g_W2dD[128*128];
__device__ float2 g_W3D [128*128];
__device__ float2 g_Wc1D[128*128];
__device__ float2 g_W4fD[256*256];
__device__ float2 g_W4dD[256*256];
__device__ float2 g_W5D [256*256];
__device__ float2 g_Wc2D[256*256];
// plain k-major (winner gather)
__device__ float g_W3T[128*128];
__device__ float g_W5T[256*256];

// ---------------- f32x2 helpers ----------------
__device__ __forceinline__ void ffma2(ull &c, ull a, ull b) {
    asm("fma.rn.f32x2 %0, %1, %2, %0;" : "+l"(c) : "l"(a), "l"(b));
}
__device__ __forceinline__ float2 unpack2(ull v) {
    float2 r; asm("mov.b64 {%0, %1}, %2;" : "=f"(r.x), "=f"(r.y) : "l"(v)); return r;
}

// ---------------- cp.async ----------------
__device__ __forceinline__ uint s2u(const void* p) {
    return (uint)__cvta_generic_to_shared(p);
}
__device__ __forceinline__ void cpa16(uint dst, const float4* src) {
    asm volatile("cp.async.cg.shared.global [%0], [%1], 16;" :: "r"(dst), "l"(src));
}
#define CP_COMMIT() asm volatile("cp.async.commit_group;")
#define CP_WAIT1()  asm volatile("cp.async.wait_group 1;")

__device__ __forceinline__ uint fkey(float v) {
    uint u = __float_as_uint(v);
    return (u & 0x80000000u) ? ~u : (u | 0x80000000u);
}

// ---------------- prep kernels ----------------
__global__ void transposeW(const float* __restrict__ src, float* __restrict__ dst,
                           int O, int K) {
    int idx = blockIdx.x * 256 + threadIdx.x;
    if (idx < O * K) {
        int o = idx / K, k = idx - o * K;
        dst[k * O + o] = src[idx];
    }
}
__global__ void transposeW_dup(const float* __restrict__ src, float2* __restrict__ dst,
                               int O, int K) {
    int idx = blockIdx.x * 256 + threadIdx.x;
    if (idx < O * K) {
        int o = idx / K, k = idx - o * K;
        float v = src[idx];
        dst[k * O + o] = make_float2(v, v);
    }
}
// dstD[k][o] = dup( sum_m A[o][m] * Bm[m][k] )
__global__ void composeT_dup(const float* __restrict__ A, const float* __restrict__ Bm,
                             float2* __restrict__ dstD, int n) {
    int idx = blockIdx.x * 256 + threadIdx.x;
    if (idx >= n * n) return;
    int o = idx % n, k = idx / n;
    float s = 0.f;
    for (int m = 0; m < n; ++m) s += A[o * n + m] * Bm[m * n + k];
    dstD[idx] = make_float2(s, s);
}

// pos [pt][128][3] -> posT tile-blocked [tile][c][i][64]
__global__ void transpose_pos(const float* __restrict__ pos, float* __restrict__ posT) {
    extern __shared__ float sm[];   // [64][385]
    int t = blockIdx.x, tid = threadIdx.x;
    const float4* s4 = (const float4*)(pos + (size_t)t * 24576);
    #pragma unroll
    for (int it = 0; it < 24; ++it) {
        int f4 = tid + it * 256;
        float4 v = s4[f4];
        int f = f4 * 4, pt = f / 384, c = f - pt * 384;
        float* d = sm + pt * 385 + c;
        d[0] = v.x; d[1] = v.y; d[2] = v.z; d[3] = v.w;
    }
    __syncthreads();
    float4* o4 = (float4*)(posT + (size_t)t * 24576);
    #pragma unroll
    for (int it = 0; it < 24; ++it) {
        int m4 = tid + it * 256, m = m4 * 4;
        int ci = m >> 6, p = m & 63;
        o4[m4] = make_float4(sm[p*385 + ci], sm[(p+1)*385 + ci],
                             sm[(p+2)*385 + ci], sm[(p+3)*385 + ci]);
    }
}

// biasF/biasD[seg][o][i] = sum_{c<128} W4{f,d}[o][128+c] * pact[seg][c][i]
__global__ void bias4_kernel(const float* __restrict__ W4f, const float* __restrict__ W4d,
                             const float* __restrict__ pact,
                             float* __restrict__ bF, float* __restrict__ bD)
{
    __shared__ float sp[128*3];
    int seg = blockIdx.x, o = threadIdx.x;
    for (int t = o; t < 128*3; t += 256) sp[t] = pact[(size_t)seg*128*3 + t];
    __syncthreads();
    float f0=0,f1=0,f2=0,d0=0,d1=0,d2=0;
    const float* wf = W4f + (size_t)o*256 + 128;
    const float* wd = W4d + (size_t)o*256 + 128;
    #pragma unroll 4
    for (int c = 0; c < 128; ++c) {
        float a = wf[c], b = wd[c];
        float x0 = sp[3*c], x1 = sp[3*c+1], x2 = sp[3*c+2];
        f0 += a*x0; f1 += a*x1; f2 += a*x2;
        d0 += b*x0; d1 += b*x1; d2 += b*x2;
    }
    float* pf = bF + ((size_t)seg*256 + o)*3;
    float* pd = bD + ((size_t)seg*256 + o)*3;
    pf[0]=f0; pf[1]=f1; pf[2]=f2;
    pd[0]=d0; pd[1]=d1; pd[2]=d2;
}

// ---------------- persistent fused VN layer (points-in-lanes) ----------------
// x is tile-blocked [tile][c (K)][i (3)][pt (64)].
// Weights dup'd k-major float2.  o-block = OB rows (blockIdx.x), walkers = gridDim.y.
// Thread: 4 rows x PT_PER pts x 3 coords for both F and D mats.
template<int KCH, int NOtot, int OB, bool BIAS, bool DOT>
__global__ void __launch_bounds__(256, 1)
vn_persist(const float* __restrict__ x, const int* __restrict__ segids,
           const float2* __restrict__ WfD, const float2* __restrict__ WdD,
           const float* __restrict__ bF, const float* __restrict__ bD,
           float* __restrict__ out, ull* __restrict__ cand)
{
    constexpr int K      = KCH * 64;
    constexpr int CGN    = (OB == 64) ? 16 : 32;
    constexpr int PT_PER = (OB == 64) ? 4 : 2;
    constexpr int NPAIR  = PT_PER / 2;
    constexpr int NJ     = NPAIR * 3;
    constexpr int XB     = 64 * 192;          // floats per x stage (12288)
    constexpr size_t TILE_F = (size_t)K * 192;

    extern __shared__ float smem[];
    ull* sWf = (ull*)smem;                    // [K][OB] dup'd
    ull* sWd = sWf + K * OB;
    float* sX = (float*)(sWd + K * OB);       // 2 x XB

    const int tid = threadIdx.x;
    const int rg = tid / CGN;
    const int cg = tid % CGN;
    const int obase = blockIdx.x * OB;
    const int nwalk = gridDim.y;

    // resident dup'd weights
    for (int t4 = tid; t4 < K * OB / 2; t4 += 256) {
        int k = t4 / (OB/2), o2 = t4 % (OB/2);
        ((float4*)sWf)[t4] = *(const float4*)(WfD + (size_t)k * NOtot + obase + 2*o2);
        ((float4*)sWd)[t4] = *(const float4*)(WdD + (size_t)k * NOtot + obase + 2*o2);
    }

    int tp = blockIdx.y, khp = 0;
    auto prefetch = [&](int tile, int kh, int buf) {
        const float4* s4 = (const float4*)(x + (size_t)tile * TILE_F + (size_t)kh * XB);
        float* d0 = sX + buf * XB;
        #pragma unroll
        for (int it = 0; it < 12; ++it) {
            int e = tid + it * 256;
            cpa16(s2u(d0 + e * 4), s4 + e);
        }
    };
    auto adv = [&]() { if (++khp == KCH) { khp = 0; tp += nwalk; } };

    prefetch(tp, khp, 0); CP_COMMIT(); adv();
    if (tp < NTILES) prefetch(tp, khp, 1);
    CP_COMMIT(); adv();

    int cur = 0;
    ull accF[4][NJ], accD[4][NJ];

    for (int t = blockIdx.y; t < NTILES; t += nwalk) {
        #pragma unroll
        for (int r = 0; r < 4; ++r)
            #pragma unroll
            for (int j = 0; j < NJ; ++j) { accF[r][j] = 0ull; accD[r][j] = 0ull; }

        #pragma unroll
        for (int kh = 0; kh < KCH; ++kh) {
            CP_WAIT1();
            __syncthreads();

            const float* xb0 = sX + cur * XB;
            const ull* wfb = sWf + (kh * 64) * OB + 4 * rg;
            const ull* wdb = sWd + (kh * 64) * OB + 4 * rg;
            #pragma unroll 4
            for (int k = 0; k < 64; ++k) {
                ull bq[NJ];
                const float* xb = xb0 + k * 192;
                if (OB == 64) {
                    #pragma unroll
                    for (int i = 0; i < 3; ++i) {
                        ulonglong2 q = *(const ulonglong2*)(xb + i*64 + 4*cg);
                        bq[i] = q.x; bq[3 + i] = q.y;
                    }
                } else {
                    #pragma unroll
                    for (int i = 0; i < 3; ++i)
                        bq[i] = *(const ull*)(xb + i*64 + 2*cg);
                }
                ulonglong2 af01 = *(const ulonglong2*)(wfb + (size_t)k * OB);
                ulonglong2 af23 = *(const ulonglong2*)(wfb + (size_t)k * OB + 2);
                ulonglong2 ad01 = *(const ulonglong2*)(wdb + (size_t)k * OB);
                ulonglong2 ad23 = *(const ulonglong2*)(wdb + (size_t)k * OB + 2);
                ull af[4] = { af01.x, af01.y, af23.x, af23.y };
                ull ad[4] = { ad01.x, ad01.y, ad23.x, ad23.y };
                #pragma unroll
                for (int r = 0; r < 4; ++r)
                    #pragma unroll
                    for (int j = 0; j < NJ; ++j) {
                        ffma2(accF[r][j], af[r], bq[j]);
                        ffma2(accD[r][j], ad[r], bq[j]);
                    }
            }
            __syncthreads();
            if (tp < NTILES) prefetch(tp, khp, cur);
            CP_COMMIT();
            adv();
            cur ^= 1;
        }

        const int seg = segids[t * TPTS];

        if (DOT) {
            #pragma unroll
            for (int r = 0; r < 4; ++r) {
                float dts[PT_PER];
                #pragma unroll
                for (int pr = 0; pr < NPAIR; ++pr) {
                    float2 f0 = unpack2(accF[r][pr*3+0]), e0 = unpack2(accD[r][pr*3+0]);
                    float2 f1 = unpack2(accF[r][pr*3+1]), e1 = unpack2(accD[r][pr*3+1]);
                    float2 f2 = unpack2(accF[r][pr*3+2]), e2 = unpack2(accD[r][pr*3+2]);
                    dts[2*pr]   = f0.x*e0.x + f1.x*e1.x + f2.x*e2.x;
                    dts[2*pr+1] = f0.y*e0.y + f1.y*e1.y + f2.y*e2.y;
                }
                int pt0 = t * TPTS + PT_PER * cg;
                float v = dts[0]; int idx = pt0;
                #pragma unroll
                for (int p = 1; p < PT_PER; ++p)
                    if (dts[p] > v) { v = dts[p]; idx = pt0 + p; }
                const int mmax = (OB == 64) ? 8 : 16;
                #pragma unroll
                for (int m = 1; m <= mmax; m <<= 1) {
                    float ov = __shfl_xor_sync(0xffffffffu, v, m);
                    int   oi = __shfl_xor_sync(0xffffffffu, idx, m);
                    if (ov > v || (ov == v && oi < idx)) { v = ov; idx = oi; }
                }
                if ((tid & (CGN - 1)) == 0) {
                    ull key = ((ull)fkey(v) << 32) | (uint)(~(uint)idx);
                    atomicMax(&cand[seg * NOtot + obase + 4*rg + r], key);
                }
            }
        } else {
            #pragma unroll
            for (int r = 0; r < 4; ++r) {
                int row = obase + 4*rg + r;
                float bf0=0.f,bf1=0.f,bf2=0.f,bd0=0.f,bd1=0.f,bd2=0.f;
                if (BIAS) {
                    const float* pf = bF + ((size_t)seg*NOtot + row)*3;
                    const float* pd = bD + ((size_t)seg*NOtot + row)*3;
                    bf0=pf[0]; bf1=pf[1]; bf2=pf[2];
                    bd0=pd[0]; bd1=pd[1]; bd2=pd[2];
                }
                float pv[PT_PER][3], ev[PT_PER][3], res[PT_PER][3];
                #pragma unroll
                for (int pr = 0; pr < NPAIR; ++pr)
                    #pragma unroll
                    for (int i = 0; i < 3; ++i) {
                        float2 f = unpack2(accF[r][pr*3+i]);
                        float2 e = unpack2(accD[r][pr*3+i]);
                        pv[2*pr][i]   = f.x; pv[2*pr+1][i]   = f.y;
                        ev[2*pr][i]   = e.x; ev[2*pr+1][i]   = e.y;
                    }
                #pragma unroll
                for (int p = 0; p < PT_PER; ++p) {
                    float p0 = pv[p][0]+bf0, p1 = pv[p][1]+bf1, p2 = pv[p][2]+bf2;
                    float e0 = ev[p][0]+bd0, e1 = ev[p][1]+bd1, e2 = ev[p][2]+bd2;
                    float dt = p0*e0 + p1*e1 + p2*e2;
                    float dn = e0*e0 + e1*e1 + e2*e2;
                    float s = dt / (dn + EPSV);
                    if (dt >= 0.f) { res[p][0]=p0;       res[p][1]=p1;       res[p][2]=p2; }
                    else           { res[p][0]=p0-s*e0;  res[p][1]=p1-s*e1;  res[p][2]=p2-s*e2; }
                }
                float* ob = out + ((size_t)t * NOtot + row) * 192 + PT_PER * cg;
                #pragma unroll
                for (int i = 0; i < 3; ++i) {
                    if (OB == 64)
                        *(float4*)(ob + i*64) = make_float4(res[0][i], res[1][i], res[2][i], res[3][i]);
                    else
                        *(float2*)(ob + i*64) = make_float2(res[0][i], res[1][i]);
                }
            }
        }
    }
}

// ---------------- winner recompute + gather (tile-blocked src) ----------------
template<int KSRC, int NOtot>
__global__ void winner_gather(const ull* __restrict__ cand, const float* __restrict__ src,
                              const float* __restrict__ WT, float* __restrict__ pooled)
{
    int seg = blockIdx.x, ch = threadIdx.x;
    ull cv = cand[seg * NOtot + ch];
    uint idx = ~((uint)(cv & 0xffffffffull));
    int tile = idx >> 6, p = idx & 63;
    const float* base = src + (size_t)tile * KSRC * 192 + p;
    float a0 = 0.f, a1 = 0.f, a2 = 0.f;
    #pragma unroll 4
    for (int c = 0; c < KSRC; ++c) {
        float w = WT[(size_t)c * NOtot + ch];
        const float* b = base + (size_t)c * 192;
        a0 += w * b[0]; a1 += w * b[64]; a2 += w * b[128];
    }
    float* o = pooled + ((size_t)seg * NOtot + ch) * 3;
    o[0] = a0; o[1] = a1; o[2] = a2;
}

// ---------------- small VNLeakyReLU on pooled [B, C, 3] ----------------
__global__ void relu_small(const float* __restrict__ pooled, const float* __restrict__ Wr,
                           float* __restrict__ out, int C)
{
    __shared__ float sx[256 * 3];
    int seg = blockIdx.x, c = threadIdx.x;
    for (int t = c; t < C * 3; t += blockDim.x) sx[t] = pooled[(size_t)seg * C * 3 + t];
    __syncthreads();
    float d0 = 0.f, d1 = 0.f, d2 = 0.f;
    const float* w = Wr + (size_t)c * C;
    for (int k = 0; k < C; ++k) {
        float wv = w[k];
        d0 += wv * sx[3*k]; d1 += wv * sx[3*k+1]; d2 += wv * sx[3*k+2];
    }
    float x0 = sx[3*c], x1 = sx[3*c+1], x2 = sx[3*c+2];
    float dt = x0*d0 + x1*d1 + x2*d2;
    float dn = d0*d0 + d1*d1 + d2*d2;
    float s = dt / (dn + EPSV);
    float* o = out + (size_t)seg * C * 3 + 3 * c;
    if (dt >= 0.f) { o[0] = x0;        o[1] = x1;        o[2] = x2; }
    else           { o[0] = x0 - s*d0; o[1] = x1 - s*d1; o[2] = x2 - s*d2; }
}

// ---------------- host launcher ----------------
extern "C" void kernel_launch(void* const* d_in, const int* in_sizes, int n_in,
                              void* d_out, int out_size)
{
    const float* pos    = (const float*)d_in[0];
    const int*   segids = (const int*)  d_in[1];
    const float* W1f = (const float*)d_in[2];
    const float* W1d = (const float*)d_in[3];
    const float* W2f = (const float*)d_in[4];
    const float* W2d = (const float*)d_in[5];
    const float* W3  = (const float*)d_in[6];
    const float* Wd1 = (const float*)d_in[7];
    const float* Wr3 = (const float*)d_in[8];
    const float* W4f = (const float*)d_in[9];
    const float* W4d = (const float*)d_in[10];
    const float* W5  = (const float*)d_in[11];
    const float* Wd2 = (const float*)d_in[12];
    const float* Wr5 = (const float*)d_in[13];
    float* outp = (float*)d_out;

    float *posT, *bufA, *bufB, *buf4, *praw, *pact, *bF, *bD;
    float *W3T, *W5T;
    float2 *W1fD, *W1dD, *W2fD, *W2dD, *W3D, *Wc1D, *W4fD, *W4dD, *W5D, *Wc2D;
    ull* cand;
    cudaGetSymbolAddress((void**)&posT, g_posT);
    cudaGetSymbolAddress((void**)&bufA, g_bufA);
    cudaGetSymbolAddress((void**)&bufB, g_bufB);
    cudaGetSymbolAddress((void**)&buf4, g_buf4);
    cudaGetSymbolAddress((void**)&praw, g_praw);
    cudaGetSymbolAddress((void**)&pact, g_pact);
    cudaGetSymbolAddress((void**)&bF,   g_biasF);
    cudaGetSymbolAddress((void**)&bD,   g_biasD);
    cudaGetSymbolAddress((void**)&cand, g_cand);
    cudaGetSymbolAddress((void**)&W1fD, g_W1fD);
    cudaGetSymbolAddress((void**)&W1dD, g_W1dD);
    cudaGetSymbolAddress((void**)&W2fD, g_W2fD);
    cudaGetSymbolAddress((void**)&W2dD, g_W2dD);
    cudaGetSymbolAddress((void**)&W3D,  g_W3D);
    cudaGetSymbolAddress((void**)&Wc1D, g_Wc1D);
    cudaGetSymbolAddress((void**)&W4fD, g_W4fD);
    cudaGetSymbolAddress((void**)&W4dD, g_W4dD);
    cudaGetSymbolAddress((void**)&W5D,  g_W5D);
    cudaGetSymbolAddress((void**)&Wc2D, g_Wc2D);
    cudaGetSymbolAddress((void**)&W3T,  g_W3T);
    cudaGetSymbolAddress((void**)&W5T,  g_W5T);

    // ---- prep ----
    transposeW_dup<<<64, 256>>>(W1f, W1fD, 128, 128);
    transposeW_dup<<<64, 256>>>(W1d, W1dD, 128, 128);
    transposeW_dup<<<64, 256>>>(W2f, W2fD, 128, 128);
    transposeW_dup<<<64, 256>>>(W2d, W2dD, 128, 128);
    transposeW_dup<<<64, 256>>>(W3,  W3D,  128, 128);
    transposeW_dup<<<256, 256>>>(W4f, W4fD, 256, 256);
    transposeW_dup<<<256, 256>>>(W4d, W4dD, 256, 256);
    transposeW_dup<<<256, 256>>>(W5,  W5D,  256, 256);
    transposeW<<<64, 256>>>(W3, W3T, 128, 128);
    transposeW<<<256, 256>>>(W5, W5T, 256, 256);
    composeT_dup<<<64, 256>>>(Wd1, W3, Wc1D, 128);
    composeT_dup<<<256, 256>>>(Wd2, W5, Wc2D, 256);

    const int smemT = 64 * 385 * 4;
    cudaFuncSetAttribute(transpose_pos, cudaFuncAttributeMaxDynamicSharedMemorySize, smemT);
    transpose_pos<<<NTILES, 256, smemT>>>(pos, posT);

    const int smemV = (128*64*2) * 8 + 2 * 64*192 * 4;   // 131072 + 98304 = 229376
    cudaFuncSetAttribute(vn_persist<2,128,64,false,false>, cudaFuncAttributeMaxDynamicSharedMemorySize, smemV);
    cudaFuncSetAttribute(vn_persist<2,128,64,false,true >, cudaFuncAttributeMaxDynamicSharedMemorySize, smemV);
    cudaFuncSetAttribute(vn_persist<2,256,64,true ,false>, cudaFuncAttributeMaxDynamicSharedMemorySize, smemV);
    cudaFuncSetAttribute(vn_persist<4,256,32,false,true >, cudaFuncAttributeMaxDynamicSharedMemorySize, smemV);

    // ---- vn1, vn2 ----
    vn_persist<2,128,64,false,false><<<dim3(2,74), 256, smemV>>>(posT, segids, W1fD, W1dD, nullptr, nullptr, bufA, nullptr);
    vn_persist<2,128,64,false,false><<<dim3(2,74), 256, smemV>>>(bufA, segids, W2fD, W2dD, nullptr, nullptr, bufB, nullptr);

    // ---- vn3 + fused pool1 argmax ----
    cudaMemsetAsync(cand, 0, BSEG*256*sizeof(ull));
    vn_persist<2,128,64,false,true ><<<dim3(2,74), 256, smemV>>>(bufB, segids, W3D, Wc1D, nullptr, nullptr, nullptr, cand);
    winner_gather<128,128><<<BSEG, 128>>>(cand, bufB, W3T, praw);
    relu_small<<<BSEG, 128>>>(praw, Wr3, pact, 128);

    // ---- vn4 (concat half folded into per-segment bias) ----
    bias4_kernel<<<BSEG, 256>>>(W4f, W4d, pact, bF, bD);
    vn_persist<2,256,64,true ,false><<<dim3(4,37), 256, smemV>>>(posT, segids, W4fD, W4dD, bF, bD, buf4, nullptr);

    // ---- vn5 + fused pool2 argmax ----
    cudaMemsetAsync(cand, 0, BSEG*256*sizeof(ull));
    vn_persist<4,256,32,false,true ><<<dim3(8,18), 256, smemV>>>(buf4, segids, W5D, Wc2D, nullptr, nullptr, nullptr, cand);
    winner_gather<256,256><<<BSEG, 256>>>(cand, buf4, W5T, praw);
    relu_small<<<BSEG, 256>>>(praw, Wr5, outp, 256);

    (void)in_sizes; (void)n_in; (void)out_size;
}